// round 7
// baseline (speedup 1.0000x reference)
#include <cuda_runtime.h>
#include <cuda_bf16.h>
#include <math.h>
#include <stdint.h>

#define D_MODEL   256
#define D_INNER   512
#define CONV_CH   640
#define D_IN_PROJ 1160
#define NPAD1     1280
#define SEQ       64
#define NSEQ      512
#define NTOK      32768
#define KFIN      1024

// ---------------- scratch ------------------------------------------------------
__device__ float         g_Zh  [(size_t)NTOK * NPAD1];
__device__ float         g_Zv  [(size_t)NTOK * NPAD1];
__device__ __nv_bfloat16 g_Xhi [(size_t)NTOK * D_MODEL];
__device__ __nv_bfloat16 g_Xlo [(size_t)NTOK * D_MODEL];
__device__ __nv_bfloat16 g_Whhi[(size_t)NPAD1 * D_MODEL];
__device__ __nv_bfloat16 g_Whlo[(size_t)NPAD1 * D_MODEL];
__device__ __nv_bfloat16 g_Wvhi[(size_t)NPAD1 * D_MODEL];
__device__ __nv_bfloat16 g_Wvlo[(size_t)NPAD1 * D_MODEL];
__device__ __nv_bfloat16 g_Yhi [(size_t)NTOK * KFIN];
__device__ __nv_bfloat16 g_Ylo [(size_t)NTOK * KFIN];
__device__ __nv_bfloat16 g_WcBhi[(size_t)D_MODEL * KFIN];
__device__ __nv_bfloat16 g_WcBlo[(size_t)D_MODEL * KFIN];

// ---------------- helpers ------------------------------------------------------
__device__ __forceinline__ uint32_t smem_u32(const void* p) {
    uint32_t a;
    asm("{ .reg .u64 t; cvta.to.shared.u64 t, %1; cvt.u32.u64 %0, t; }" : "=r"(a) : "l"(p));
    return a;
}
__device__ __forceinline__ uint32_t sw64(uint32_t off) {   // 64B-row swizzle
    return off ^ ((off >> 3) & 0x30);
}
#define CP16(dst, src) \
    asm volatile("cp.async.cg.shared.global [%0], [%1], 16;" :: "r"(dst), "l"(src))
#define CP_COMMIT() asm volatile("cp.async.commit_group;" ::: "memory")
#define CP_WAIT(n)  asm volatile("cp.async.wait_group %0;" :: "n"(n) : "memory")

typedef unsigned long long ull;
__device__ __forceinline__ ull pack2(float lo, float hi) {
    ull r; asm("mov.b64 %0, {%1, %2};" : "=l"(r) : "f"(lo), "f"(hi)); return r;
}
#define FMA_X2(d, a, b, c) \
    asm("fma.rn.f32x2 %0, %1, %2, %3;" : "=l"(d) : "l"(a), "l"(b), "l"(c))
#define MUL_X2(d, a, b) \
    asm("mul.rn.f32x2 %0, %1, %2;" : "=l"(d) : "l"(a), "l"(b))

// ---------------- conversion kernels -------------------------------------------
__global__ void cvt_x_kernel(const float* __restrict__ in) {
    size_t i = (size_t)blockIdx.x * 256 + threadIdx.x;
    float4 v = ((const float4*)in)[i];
    __nv_bfloat16 h0 = __float2bfloat16(v.x), h1 = __float2bfloat16(v.y);
    __nv_bfloat16 h2 = __float2bfloat16(v.z), h3 = __float2bfloat16(v.w);
    __nv_bfloat162 hi01; hi01.x = h0; hi01.y = h1;
    __nv_bfloat162 hi23; hi23.x = h2; hi23.y = h3;
    __nv_bfloat162 lo01, lo23;
    lo01.x = __float2bfloat16(v.x - __bfloat162float(h0));
    lo01.y = __float2bfloat16(v.y - __bfloat162float(h1));
    lo23.x = __float2bfloat16(v.z - __bfloat162float(h2));
    lo23.y = __float2bfloat16(v.w - __bfloat162float(h3));
    ((__nv_bfloat162*)g_Xhi)[2 * i]     = hi01;
    ((__nv_bfloat162*)g_Xhi)[2 * i + 1] = hi23;
    ((__nv_bfloat162*)g_Xlo)[2 * i]     = lo01;
    ((__nv_bfloat162*)g_Xlo)[2 * i + 1] = lo23;
}

__global__ void prep_w_kernel(const float* __restrict__ wh, const float* __restrict__ wv) {
    int i = blockIdx.x * 256 + threadIdx.x;
    const float* w = blockIdx.y ? wv : wh;
    __nv_bfloat16* whi = blockIdx.y ? g_Wvhi : g_Whhi;
    __nv_bfloat16* wlo = blockIdx.y ? g_Wvlo : g_Whlo;
    if (i < NPAD1 * D_MODEL) {
        int n = i >> 8;
        float v = (n < D_IN_PROJ) ? w[i] : 0.f;
        __nv_bfloat16 h = __float2bfloat16(v);
        whi[i] = h;
        wlo[i] = __float2bfloat16(v - __bfloat162float(h));
    }
}

// ---------------- mma.sync split-bf16 GEMM --------------------------------------
// C = Ahi*Bhi + Ahi*Blo + Alo*Bhi, single K pass. A:[M][K], B:[N][K] k-major.
// Tile 128x128, 4 warps (2x2), warp 64x64, BK=32, 3-stage ring, 2 CTAs/SM.
#define BMg 128
#define BNg 128
#define TILE_Bg  8192            // 128x32 bf16
#define STAGE_Bg 32768           // 4 tiles
#define GSMEM    (3 * STAGE_Bg)  // 98304

__global__ void __launch_bounds__(128, 2) gemm_mma(
    const __nv_bfloat16* __restrict__ Ahi, const __nv_bfloat16* __restrict__ Alo,
    const __nv_bfloat16* __restrict__ B0hi, const __nv_bfloat16* __restrict__ B0lo,
    const __nv_bfloat16* __restrict__ B1hi, const __nv_bfloat16* __restrict__ B1lo,
    float* __restrict__ C0, float* __restrict__ C1,
    int K, int ldc, const float* __restrict__ bias)
{
    extern __shared__ __nv_bfloat16 sm[];
    const uint32_t smb = smem_u32(sm);
    const int tid = threadIdx.x, lane = tid & 31, wid = tid >> 5;
    const int m0 = blockIdx.y * BMg, n0 = blockIdx.x * BNg;   // n fastest: A reuse in L2
    const int wm = (wid & 1) * 64, wn = (wid >> 1) * 64;
    const int nk = K >> 5;

    const __nv_bfloat16* Bhi = blockIdx.z ? B1hi : B0hi;
    const __nv_bfloat16* Blo = blockIdx.z ? B1lo : B0lo;
    float* C = blockIdx.z ? C1 : C0;

    uint32_t arow[4], brow[4];
#pragma unroll
    for (int mt = 0; mt < 4; mt++)
        arow[mt] = (uint32_t)(wm + mt * 16 + (lane & 15)) * 64 + (lane >> 4) * 16;
#pragma unroll
    for (int nb = 0; nb < 4; nb++)
        brow[nb] = (uint32_t)(wn + nb * 16 + (lane & 15)) * 64 + (lane >> 4) * 16;

    float acc[4][8][4];
#pragma unroll
    for (int a = 0; a < 4; a++)
#pragma unroll
        for (int b = 0; b < 8; b++)
#pragma unroll
            for (int c = 0; c < 4; c++) acc[a][b][c] = 0.f;

    auto load_stage = [&](int s, int c) {
        const int koff = c * 32;
        const uint32_t base = smb + s * STAGE_Bg;
        const __nv_bfloat16* pAhi = Ahi + (size_t)(m0 + tid) * K + koff;
        const __nv_bfloat16* pAlo = Alo + (size_t)(m0 + tid) * K + koff;
        const __nv_bfloat16* pBhi = Bhi + (size_t)(n0 + tid) * K + koff;
        const __nv_bfloat16* pBlo = Blo + (size_t)(n0 + tid) * K + koff;
        const uint32_t rb = (uint32_t)tid * 64;
#pragma unroll
        for (int ch = 0; ch < 4; ch++) {
            uint32_t d = sw64(rb + ch * 16);
            CP16(base + d, pAhi + ch * 8);
            CP16(base + TILE_Bg + d, pAlo + ch * 8);
            CP16(base + 2 * TILE_Bg + d, pBhi + ch * 8);
            CP16(base + 3 * TILE_Bg + d, pBlo + ch * 8);
        }
        CP_COMMIT();
    };

    load_stage(0, 0);
    load_stage(1, 1);

    for (int c = 0; c < nk; c++) {
        if (c + 1 < nk) CP_WAIT(1); else CP_WAIT(0);
        __syncthreads();
        if (c + 2 < nk) load_stage((c + 2) % 3, c + 2);

        const uint32_t base = smb + (c % 3) * STAGE_Bg;
        const uint32_t aHiB = base, aLoB = base + TILE_Bg;
        const uint32_t bHiB = base + 2 * TILE_Bg, bLoB = base + 3 * TILE_Bg;
#pragma unroll
        for (int ks = 0; ks < 2; ks++) {
            uint32_t ahi[4][4], alo[4][4], bhi[4][4], blo[4][4];
#pragma unroll
            for (int mt = 0; mt < 4; mt++) {
                uint32_t sw = sw64(arow[mt] + ks * 32);
                asm volatile("ldmatrix.sync.aligned.m8n8.x4.shared.b16 {%0,%1,%2,%3}, [%4];"
                             : "=r"(ahi[mt][0]), "=r"(ahi[mt][1]), "=r"(ahi[mt][2]), "=r"(ahi[mt][3])
                             : "r"(aHiB + sw));
                asm volatile("ldmatrix.sync.aligned.m8n8.x4.shared.b16 {%0,%1,%2,%3}, [%4];"
                             : "=r"(alo[mt][0]), "=r"(alo[mt][1]), "=r"(alo[mt][2]), "=r"(alo[mt][3])
                             : "r"(aLoB + sw));
            }
#pragma unroll
            for (int nb = 0; nb < 4; nb++) {
                uint32_t sw = sw64(brow[nb] + ks * 32);
                asm volatile("ldmatrix.sync.aligned.m8n8.x4.shared.b16 {%0,%1,%2,%3}, [%4];"
                             : "=r"(bhi[nb][0]), "=r"(bhi[nb][1]), "=r"(bhi[nb][2]), "=r"(bhi[nb][3])
                             : "r"(bHiB + sw));
                asm volatile("ldmatrix.sync.aligned.m8n8.x4.shared.b16 {%0,%1,%2,%3}, [%4];"
                             : "=r"(blo[nb][0]), "=r"(blo[nb][1]), "=r"(blo[nb][2]), "=r"(blo[nb][3])
                             : "r"(bLoB + sw));
            }
#define MMA_PASS(AF, BF)                                                              \
            _Pragma("unroll")                                                         \
            for (int mt = 0; mt < 4; mt++)                                            \
                _Pragma("unroll")                                                     \
                for (int nb = 0; nb < 4; nb++) {                                      \
                    asm volatile(                                                     \
                        "mma.sync.aligned.m16n8k16.row.col.f32.bf16.bf16.f32 "        \
                        "{%0,%1,%2,%3}, {%4,%5,%6,%7}, {%8,%9}, {%0,%1,%2,%3};"       \
                        : "+f"(acc[mt][nb * 2][0]), "+f"(acc[mt][nb * 2][1]),         \
                          "+f"(acc[mt][nb * 2][2]), "+f"(acc[mt][nb * 2][3])          \
                        : "r"(AF[mt][0]), "r"(AF[mt][1]), "r"(AF[mt][2]), "r"(AF[mt][3]), \
                          "r"(BF[nb][0]), "r"(BF[nb][2]));                            \
                    asm volatile(                                                     \
                        "mma.sync.aligned.m16n8k16.row.col.f32.bf16.bf16.f32 "        \
                        "{%0,%1,%2,%3}, {%4,%5,%6,%7}, {%8,%9}, {%0,%1,%2,%3};"       \
                        : "+f"(acc[mt][nb * 2 + 1][0]), "+f"(acc[mt][nb * 2 + 1][1]), \
                          "+f"(acc[mt][nb * 2 + 1][2]), "+f"(acc[mt][nb * 2 + 1][3])  \
                        : "r"(AF[mt][0]), "r"(AF[mt][1]), "r"(AF[mt][2]), "r"(AF[mt][3]), \
                          "r"(BF[nb][1]), "r"(BF[nb][3]));                            \
                }
            MMA_PASS(ahi, bhi)
            MMA_PASS(ahi, blo)
            MMA_PASS(alo, bhi)
#undef MMA_PASS
        }
    }

#pragma unroll
    for (int mt = 0; mt < 4; mt++) {
        int row = m0 + wm + mt * 16 + (lane >> 2);
#pragma unroll
        for (int nt = 0; nt < 8; nt++) {
            int col = n0 + wn + nt * 8 + (lane & 3) * 2;
            float2 v0 = make_float2(acc[mt][nt][0], acc[mt][nt][1]);
            float2 v1 = make_float2(acc[mt][nt][2], acc[mt][nt][3]);
            if (bias) {
                float b0 = bias[col], b1 = bias[col + 1];
                v0.x += b0; v0.y += b1; v1.x += b0; v1.y += b1;
            }
            *(float2*)&C[(size_t)row * ldc + col] = v0;
            *(float2*)&C[(size_t)(row + 8) * ldc + col] = v1;
        }
    }
}

// ---------------- fused conv + SiLU + softplus + SSM scan + gate + RMSnorm ------
__global__ void __launch_bounds__(512, 1) scan_kernel(
    const float* __restrict__ cwh, const float* __restrict__ cbh,
    const float* __restrict__ dtbh, const float* __restrict__ Alh,
    const float* __restrict__ Dh_, const float* __restrict__ nwh,
    const float* __restrict__ cwv, const float* __restrict__ cbv,
    const float* __restrict__ dtbv, const float* __restrict__ Alv,
    const float* __restrict__ Dv_, const float* __restrict__ nwv)
{
    const int tid  = threadIdx.x;
    const int head = tid >> 6;
    const int dir  = blockIdx.x >> 9;
    const int s    = blockIdx.x & 511;

    const float* Z       = dir ? g_Zv : g_Zh;
    const float* conv_w  = dir ? cwv : cwh;
    const float* conv_b  = dir ? cbv : cbh;
    const float* dt_bias = dir ? dtbv : dtbh;
    const float* A_log   = dir ? Alv : Alh;
    const float* Dvv     = dir ? Dv_ : Dh_;
    const float* norm_w  = dir ? nwv : nwh;
    const int ycol_off   = dir ? 0 : 512;

    int base, stride;
    if (dir) { int b = s >> 6, w = s & 63; base = b * 4096 + w; stride = 64; }
    else     { base = s * 64; stride = 1; }

    __shared__ __align__(16) float ring[8][CONV_CH];
    __shared__ __align__(16) float zbuf[4][512];
    __shared__ __align__(16) float dtbuf[4][8];
    __shared__ __align__(16) float Bsh[64];
    __shared__ __align__(16) float Csh[64];
    __shared__ float dt_s[8], dA_s[8], Aneg_s[8], dtb_s[8];
    __shared__ float red[16];

    for (int i = tid; i < 8 * CONV_CH; i += 512) (&ring[0][0])[i] = 0.f;
    if (tid < 8) { Aneg_s[tid] = -expf(A_log[tid]); dtb_s[tid] = dt_bias[tid]; }

    const float w0 = conv_w[tid * 4 + 0], w1 = conv_w[tid * 4 + 1];
    const float w2 = conv_w[tid * 4 + 2], w3 = conv_w[tid * 4 + 3];
    const float cb = conv_b[tid];
    float u0 = 0.f, u1 = 0.f, u2 = 0.f, u3 = 0.f, cb2 = 0.f;
    const int c2 = 512 + tid;
    if (tid < 128) {
        u0 = conv_w[c2 * 4 + 0]; u1 = conv_w[c2 * 4 + 1];
        u2 = conv_w[c2 * 4 + 2]; u3 = conv_w[c2 * 4 + 3];
        cb2 = conv_b[c2];
    }
    const float Dhv = Dvv[head];
    const float nw = norm_w[tid];

    ull h2[32];
#pragma unroll
    for (int n = 0; n < 32; n++) h2[n] = pack2(0.f, 0.f);

    const uint32_t ring_b = smem_u32(&ring[0][0]);
    const uint32_t zbuf_b = smem_u32(&zbuf[0][0]);
    const uint32_t dtb_b  = smem_u32(&dtbuf[0][0]);

    auto prefetch = [&](int tt) {
        if (tt < SEQ) {
            const float* row = Z + (size_t)(base + tt * stride) * NPAD1;
            if (tid < 160)       CP16(ring_b + (tt & 7) * (CONV_CH * 4) + tid * 16, row + 512 + tid * 4);
            else if (tid < 288)  CP16(zbuf_b + (tt & 3) * 2048 + (tid - 160) * 16, row + (tid - 160) * 4);
            else if (tid < 290)  CP16(dtb_b + (tt & 3) * 32 + (tid - 288) * 16, row + 1152 + (tid - 288) * 4);
        }
        CP_COMMIT();
    };

    __syncthreads();
    prefetch(0);
    prefetch(1);

    for (int t = 0; t < SEQ; t++) {
        if (t < SEQ - 1) CP_WAIT(1); else CP_WAIT(0);
        __syncthreads();
        prefetch(t + 2);

        const int slot = t & 7;
        if (tid < 8) {
            float draw = dtbuf[t & 3][tid] + dtb_s[tid];
            float dt = (draw > 20.f) ? draw : log1pf(expf(draw));
            dt_s[tid] = dt;
            dA_s[tid] = expf(dt * Aneg_s[tid]);
        }

        const int s0 = (t + 5) & 7, s1 = (t + 6) & 7, s2 = (t + 7) & 7, s3 = slot;
        float xv = cb;
        xv = fmaf(ring[s0][tid], w0, xv);
        xv = fmaf(ring[s1][tid], w1, xv);
        xv = fmaf(ring[s2][tid], w2, xv);
        xv = fmaf(ring[s3][tid], w3, xv);
        xv = xv / (1.f + expf(-xv));
        if (tid < 128) {
            float v = cb2;
            v = fmaf(ring[s0][c2], u0, v);
            v = fmaf(ring[s1][c2], u1, v);
            v = fmaf(ring[s2][c2], u2, v);
            v = fmaf(ring[s3][c2], u3, v);
            v = v / (1.f + expf(-v));
            if (tid < 64) Bsh[tid] = v; else Csh[tid - 64] = v;
        }
        __syncthreads();

        const float dA  = dA_s[head];
        const float dtx = dt_s[head] * xv;
        const ull dA2  = pack2(dA, dA);
        const ull dtx2 = pack2(dtx, dtx);
        ull y2 = pack2(0.f, 0.f);
        const ull* B2 = (const ull*)Bsh;
        const ull* C2 = (const ull*)Csh;
#pragma unroll
        for (int n = 0; n < 32; n++) {
            ull tb;
            MUL_X2(tb, dtx2, B2[n]);
            FMA_X2(h2[n], h2[n], dA2, tb);
            FMA_X2(y2, h2[n], C2[n], y2);
        }
        float ylo, yhi;
        asm("mov.b64 {%0, %1}, %2;" : "=f"(ylo), "=f"(yhi) : "l"(y2));
        float y = ylo + yhi;
        y = fmaf(xv, Dhv, y);

        const float z = zbuf[t & 3][tid];
        float g = y * (z / (1.f + expf(-z)));
        float ss = g * g;
#pragma unroll
        for (int o = 16; o; o >>= 1) ss += __shfl_xor_sync(0xffffffffu, ss, o);
        if ((tid & 31) == 0) red[tid >> 5] = ss;
        __syncthreads();
        float v = red[tid & 15];
#pragma unroll
        for (int o = 8; o; o >>= 1) v += __shfl_xor_sync(0xffffffffu, v, o);
        float s_inv = rsqrtf(v * (1.0f / 512.0f) + 1e-5f);

        float val = g * s_inv * nw;
        __nv_bfloat16 hh = __float2bfloat16(val);
        size_t oidx = (size_t)(base + t * stride) * KFIN + ycol_off + tid;
        g_Yhi[oidx] = hh;
        g_Ylo[oidx] = __float2bfloat16(val - __bfloat162float(hh));
    }
}

// ---------------- fold fc_w into out_w -----------------------------------------
__global__ void __launch_bounds__(256) wcomb_kernel(
    const float* __restrict__ mh_out_w, const float* __restrict__ mv_out_w,
    const float* __restrict__ fc_w)
{
    const int d  = blockIdx.x;
    const int k0 = blockIdx.y * 64;
    const int nb = blockIdx.z * 32;
    const float* ow = d ? mh_out_w : mv_out_w;
    const int fo = d ? 512 : 0;
    __shared__ float ows[64][65];
    __shared__ float fs[32][65];
    const int kk = threadIdx.x & 63;
    const int ng = threadIdx.x >> 6;
    float acc[8];
#pragma unroll
    for (int i = 0; i < 8; i++) acc[i] = 0.f;

    for (int jo = 0; jo < 256; jo += 64) {
        for (int idx = threadIdx.x; idx < 64 * 64; idx += 256) {
            int j = idx >> 6, c = idx & 63;
            ows[j][c] = ow[(size_t)(jo + j) * 512 + k0 + c];
        }
        for (int idx = threadIdx.x; idx < 32 * 64; idx += 256) {
            int n = idx >> 6, jj = idx & 63;
            fs[n][jj] = fc_w[(size_t)(nb + n) * 1024 + fo + jo + jj] +
                        fc_w[(size_t)(nb + n) * 1024 + fo + 256 + jo + jj];
        }
        __syncthreads();
#pragma unroll 4
        for (int j = 0; j < 64; j++) {
            float o = ows[j][kk];
#pragma unroll
            for (int i = 0; i < 8; i++)
                acc[i] = fmaf(o, fs[ng * 8 + i][j], acc[i]);
        }
        __syncthreads();
    }
#pragma unroll
    for (int i = 0; i < 8; i++) {
        float val = acc[i];
        __nv_bfloat16 hh = __float2bfloat16(val);
        size_t idx = (size_t)(nb + ng * 8 + i) * KFIN + d * 512 + (k0 + kk);
        g_WcBhi[idx] = hh;
        g_WcBlo[idx] = __float2bfloat16(val - __bfloat162float(hh));
    }
}

// ---------------- launch ----------------
extern "C" void kernel_launch(void* const* d_in, const int* in_sizes, int n_in,
                              void* d_out, int out_size)
{
    (void)in_sizes; (void)n_in; (void)out_size;
    const float* x          = (const float*)d_in[0];
    const float* mh_in_w    = (const float*)d_in[1];
    const float* mh_conv_w  = (const float*)d_in[2];
    const float* mh_conv_b  = (const float*)d_in[3];
    const float* mh_dt_bias = (const float*)d_in[4];
    const float* mh_A_log   = (const float*)d_in[5];
    const float* mh_D       = (const float*)d_in[6];
    const float* mh_norm_w  = (const float*)d_in[7];
    const float* mh_out_w   = (const float*)d_in[8];
    const float* mv_in_w    = (const float*)d_in[9];
    const float* mv_conv_w  = (const float*)d_in[10];
    const float* mv_conv_b  = (const float*)d_in[11];
    const float* mv_dt_bias = (const float*)d_in[12];
    const float* mv_A_log   = (const float*)d_in[13];
    const float* mv_D       = (const float*)d_in[14];
    const float* mv_norm_w  = (const float*)d_in[15];
    const float* mv_out_w   = (const float*)d_in[16];
    const float* fc_w       = (const float*)d_in[17];
    const float* fc_b       = (const float*)d_in[18];
    float* out = (float*)d_out;

    float *Zh, *Zv;
    __nv_bfloat16 *Xhi, *Xlo, *Whhi, *Whlo, *Wvhi, *Wvlo, *Yhi, *Ylo, *WcBhi, *WcBlo;
    cudaGetSymbolAddress((void**)&Zh,   g_Zh);
    cudaGetSymbolAddress((void**)&Zv,   g_Zv);
    cudaGetSymbolAddress((void**)&Xhi,  g_Xhi);
    cudaGetSymbolAddress((void**)&Xlo,  g_Xlo);
    cudaGetSymbolAddress((void**)&Whhi, g_Whhi);
    cudaGetSymbolAddress((void**)&Whlo, g_Whlo);
    cudaGetSymbolAddress((void**)&Wvhi, g_Wvhi);
    cudaGetSymbolAddress((void**)&Wvlo, g_Wvlo);
    cudaGetSymbolAddress((void**)&Yhi,  g_Yhi);
    cudaGetSymbolAddress((void**)&Ylo,  g_Ylo);
    cudaGetSymbolAddress((void**)&WcBhi, g_WcBhi);
    cudaGetSymbolAddress((void**)&WcBlo, g_WcBlo);

    cudaFuncSetAttribute(gemm_mma, cudaFuncAttributeMaxDynamicSharedMemorySize, GSMEM);

    cvt_x_kernel<<<NTOK * D_MODEL / 4 / 256, 256>>>(x);
    prep_w_kernel<<<dim3((NPAD1 * D_MODEL + 255) / 256, 2), 256>>>(mh_in_w, mv_in_w);
    wcomb_kernel<<<dim3(2, 8, 8), 256>>>(mh_out_w, mv_out_w, fc_w);

    // both in-proj GEMMs in one launch (x = n for A-tile L2 reuse, y = m, z = dir)
    gemm_mma<<<dim3(NPAD1 / BNg, NTOK / BMg, 2), 128, GSMEM>>>(
        Xhi, Xlo, Whhi, Whlo, Wvhi, Wvlo, Zh, Zv, D_MODEL, NPAD1, nullptr);

    // both scans in one launch
    scan_kernel<<<2 * NSEQ, 512>>>(
        mh_conv_w, mh_conv_b, mh_dt_bias, mh_A_log, mh_D, mh_norm_w,
        mv_conv_w, mv_conv_b, mv_dt_bias, mv_A_log, mv_D, mv_norm_w);

    // final fused output GEMM
    gemm_mma<<<dim3(D_MODEL / BNg, NTOK / BMg, 1), 128, GSMEM>>>(
        Yhi, Ylo, WcBhi, WcBlo, WcBhi, WcBlo, out, out, KFIN, D_MODEL, fc_b);
}

// round 8
// speedup vs baseline: 1.1843x; 1.1843x over previous
#include <cuda_runtime.h>
#include <cuda_bf16.h>
#include <cuda_fp16.h>
#include <math.h>
#include <stdint.h>

#define D_MODEL   256
#define D_INNER   512
#define CONV_CH   640
#define D_IN_PROJ 1160
#define NPAD1     1280
#define SEQ       64
#define NSEQ      512
#define NTOK      32768
#define KFIN      1024

// ---------------- scratch ------------------------------------------------------
__device__ float  g_Zh  [(size_t)NTOK * NPAD1];
__device__ float  g_Zv  [(size_t)NTOK * NPAD1];
__device__ __half g_Xhi [(size_t)NTOK * D_MODEL];
__device__ __half g_Xlo [(size_t)NTOK * D_MODEL];
__device__ __half g_Whhi[(size_t)NPAD1 * D_MODEL];
__device__ __half g_Whlo[(size_t)NPAD1 * D_MODEL];
__device__ __half g_Wvhi[(size_t)NPAD1 * D_MODEL];
__device__ __half g_Wvlo[(size_t)NPAD1 * D_MODEL];
__device__ __half g_Y   [(size_t)NTOK * KFIN];
__device__ __half g_WcBhi[(size_t)D_MODEL * KFIN];
__device__ __half g_WcBlo[(size_t)D_MODEL * KFIN];

// ---------------- helpers ------------------------------------------------------
__device__ __forceinline__ uint32_t smem_u32(const void* p) {
    uint32_t a;
    asm("{ .reg .u64 t; cvta.to.shared.u64 t, %1; cvt.u32.u64 %0, t; }" : "=r"(a) : "l"(p));
    return a;
}
__device__ __forceinline__ uint32_t sw64(uint32_t off) {   // 64B-row swizzle
    return off ^ ((off >> 3) & 0x30);
}
#define CP16(dst, src) \
    asm volatile("cp.async.cg.shared.global [%0], [%1], 16;" :: "r"(dst), "l"(src))
#define CP_COMMIT() asm volatile("cp.async.commit_group;" ::: "memory")
#define CP_WAIT(n)  asm volatile("cp.async.wait_group %0;" :: "n"(n) : "memory")

typedef unsigned long long ull;
__device__ __forceinline__ ull pack2(float lo, float hi) {
    ull r; asm("mov.b64 %0, {%1, %2};" : "=l"(r) : "f"(lo), "f"(hi)); return r;
}
#define FMA_X2(d, a, b, c) \
    asm("fma.rn.f32x2 %0, %1, %2, %3;" : "=l"(d) : "l"(a), "l"(b), "l"(c))
#define MUL_X2(d, a, b) \
    asm("mul.rn.f32x2 %0, %1, %2;" : "=l"(d) : "l"(a), "l"(b))

// ---------------- conversion kernels -------------------------------------------
__global__ void cvt_x_kernel(const float* __restrict__ in) {
    size_t i = (size_t)blockIdx.x * 256 + threadIdx.x;
    float4 v = ((const float4*)in)[i];
    __half h0 = __float2half(v.x), h1 = __float2half(v.y);
    __half h2 = __float2half(v.z), h3 = __float2half(v.w);
    __half2 hi01 = __halves2half2(h0, h1), hi23 = __halves2half2(h2, h3);
    __half2 lo01 = __halves2half2(__float2half(v.x - __half2float(h0)),
                                  __float2half(v.y - __half2float(h1)));
    __half2 lo23 = __halves2half2(__float2half(v.z - __half2float(h2)),
                                  __float2half(v.w - __half2float(h3)));
    ((__half2*)g_Xhi)[2 * i]     = hi01;
    ((__half2*)g_Xhi)[2 * i + 1] = hi23;
    ((__half2*)g_Xlo)[2 * i]     = lo01;
    ((__half2*)g_Xlo)[2 * i + 1] = lo23;
}

__global__ void prep_w_kernel(const float* __restrict__ wh, const float* __restrict__ wv) {
    int i = blockIdx.x * 256 + threadIdx.x;
    const float* w = blockIdx.y ? wv : wh;
    __half* whi = blockIdx.y ? g_Wvhi : g_Whhi;
    __half* wlo = blockIdx.y ? g_Wvlo : g_Whlo;
    if (i < NPAD1 * D_MODEL) {
        int n = i >> 8;
        float v = (n < D_IN_PROJ) ? w[i] : 0.f;
        __half h = __float2half(v);
        whi[i] = h;
        wlo[i] = __float2half(v - __half2float(h));
    }
}

// ---------------- mma.sync split-fp16 GEMM --------------------------------------
// C = A*Bhi + A*Blo (+ Alo*Bhi on the dt-containing N-tile).
// A:[M][K] fp16 k-major, B:[N][K] fp16 k-major.
// Tile 128x128, 8 warps (2x4), warp 64x32, BK=32, 3-stage ring, 2 CTAs/SM.
#define BMg 128
#define BNg 128
#define TILE_Bg  8192            // 128x32 fp16
#define STAGE_Bg 32768           // 4 tile slots (A, Alo, Bhi, Blo)
#define GSMEM    (3 * STAGE_Bg)  // 98304

__global__ void __launch_bounds__(256, 2) gemm_mma(
    const __half* __restrict__ A, const __half* __restrict__ Alo,
    const __half* __restrict__ B0hi, const __half* __restrict__ B0lo,
    const __half* __restrict__ B1hi, const __half* __restrict__ B1lo,
    float* __restrict__ C0, float* __restrict__ C1,
    int K, int ldc, const float* __restrict__ bias, int dtn)
{
    extern __shared__ __half sm[];
    const uint32_t smb = smem_u32(sm);
    const int tid = threadIdx.x, lane = tid & 31, wid = tid >> 5;
    const int m0 = blockIdx.x * BMg, n0 = blockIdx.y * BNg;
    const int wm = (wid & 1) * 64, wn = 32 * (wid >> 1);
    const int nk = K >> 5;
    const bool need3 = (n0 == dtn);

    const __half* Bhi = blockIdx.z ? B1hi : B0hi;
    const __half* Blo = blockIdx.z ? B1lo : B0lo;
    float* C = blockIdx.z ? C1 : C0;

    uint32_t arow[4], brow[2];
#pragma unroll
    for (int mt = 0; mt < 4; mt++)
        arow[mt] = (uint32_t)(wm + mt * 16 + (lane & 15)) * 64 + (lane >> 4) * 16;
#pragma unroll
    for (int nb = 0; nb < 2; nb++)
        brow[nb] = (uint32_t)(wn + nb * 16 + (lane & 15)) * 64 + (lane >> 4) * 16;

    float acc[4][4][4];
#pragma unroll
    for (int a = 0; a < 4; a++)
#pragma unroll
        for (int b = 0; b < 4; b++)
#pragma unroll
            for (int c = 0; c < 4; c++) acc[a][b][c] = 0.f;

    const int lrow = tid & 127, hf = tid >> 7;
    const uint32_t rb = (uint32_t)lrow * 64 + hf * 32;

    auto load_stage = [&](int s, int c) {
        const int koff = c * 32 + hf * 16;
        const uint32_t base = smb + s * STAGE_Bg;
        const __half* pA   = A   + (size_t)(m0 + lrow) * K + koff;
        const __half* pBhi = Bhi + (size_t)(n0 + lrow) * K + koff;
        const __half* pBlo = Blo + (size_t)(n0 + lrow) * K + koff;
#pragma unroll
        for (int ch = 0; ch < 2; ch++) {
            uint32_t d = sw64(rb + ch * 16);
            CP16(base + d, pA + ch * 8);
            CP16(base + 2 * TILE_Bg + d, pBhi + ch * 8);
            CP16(base + 3 * TILE_Bg + d, pBlo + ch * 8);
        }
        if (need3) {
            const __half* pAlo = Alo + (size_t)(m0 + lrow) * K + koff;
#pragma unroll
            for (int ch = 0; ch < 2; ch++)
                CP16(base + TILE_Bg + sw64(rb + ch * 16), pAlo + ch * 8);
        }
        CP_COMMIT();
    };

    load_stage(0, 0);
    load_stage(1, 1);

    for (int c = 0; c < nk; c++) {
        if (c + 1 < nk) CP_WAIT(1); else CP_WAIT(0);
        __syncthreads();
        if (c + 2 < nk) load_stage((c + 2) % 3, c + 2);

        const uint32_t base = smb + (c % 3) * STAGE_Bg;
        const uint32_t aB = base, aLoB = base + TILE_Bg;
        const uint32_t bHiB = base + 2 * TILE_Bg, bLoB = base + 3 * TILE_Bg;
#pragma unroll
        for (int ks = 0; ks < 2; ks++) {
            uint32_t af[4][4], alo[4][4], bhi[2][4], blo[2][4];
#pragma unroll
            for (int mt = 0; mt < 4; mt++) {
                uint32_t sw = sw64(arow[mt] + ks * 32);
                asm volatile("ldmatrix.sync.aligned.m8n8.x4.shared.b16 {%0,%1,%2,%3}, [%4];"
                             : "=r"(af[mt][0]), "=r"(af[mt][1]), "=r"(af[mt][2]), "=r"(af[mt][3])
                             : "r"(aB + sw));
            }
#pragma unroll
            for (int nb = 0; nb < 2; nb++) {
                uint32_t sw = sw64(brow[nb] + ks * 32);
                asm volatile("ldmatrix.sync.aligned.m8n8.x4.shared.b16 {%0,%1,%2,%3}, [%4];"
                             : "=r"(bhi[nb][0]), "=r"(bhi[nb][1]), "=r"(bhi[nb][2]), "=r"(bhi[nb][3])
                             : "r"(bHiB + sw));
                asm volatile("ldmatrix.sync.aligned.m8n8.x4.shared.b16 {%0,%1,%2,%3}, [%4];"
                             : "=r"(blo[nb][0]), "=r"(blo[nb][1]), "=r"(blo[nb][2]), "=r"(blo[nb][3])
                             : "r"(bLoB + sw));
            }
#define MMA_PASS(AF, BF)                                                              \
            _Pragma("unroll")                                                         \
            for (int mt = 0; mt < 4; mt++)                                            \
                _Pragma("unroll")                                                     \
                for (int nb = 0; nb < 2; nb++) {                                      \
                    asm volatile(                                                     \
                        "mma.sync.aligned.m16n8k16.row.col.f32.f16.f16.f32 "          \
                        "{%0,%1,%2,%3}, {%4,%5,%6,%7}, {%8,%9}, {%0,%1,%2,%3};"       \
                        : "+f"(acc[mt][nb * 2][0]), "+f"(acc[mt][nb * 2][1]),         \
                          "+f"(acc[mt][nb * 2][2]), "+f"(acc[mt][nb * 2][3])          \
                        : "r"(AF[mt][0]), "r"(AF[mt][1]), "r"(AF[mt][2]), "r"(AF[mt][3]), \
                          "r"(BF[nb][0]), "r"(BF[nb][2]));                            \
                    asm volatile(                                                     \
                        "mma.sync.aligned.m16n8k16.row.col.f32.f16.f16.f32 "          \
                        "{%0,%1,%2,%3}, {%4,%5,%6,%7}, {%8,%9}, {%0,%1,%2,%3};"       \
                        : "+f"(acc[mt][nb * 2 + 1][0]), "+f"(acc[mt][nb * 2 + 1][1]), \
                          "+f"(acc[mt][nb * 2 + 1][2]), "+f"(acc[mt][nb * 2 + 1][3])  \
                        : "r"(AF[mt][0]), "r"(AF[mt][1]), "r"(AF[mt][2]), "r"(AF[mt][3]), \
                          "r"(BF[nb][1]), "r"(BF[nb][3]));                            \
                }
            MMA_PASS(af, bhi)
            MMA_PASS(af, blo)
            if (need3) {
#pragma unroll
                for (int mt = 0; mt < 4; mt++) {
                    uint32_t sw = sw64(arow[mt] + ks * 32);
                    asm volatile("ldmatrix.sync.aligned.m8n8.x4.shared.b16 {%0,%1,%2,%3}, [%4];"
                                 : "=r"(alo[mt][0]), "=r"(alo[mt][1]), "=r"(alo[mt][2]), "=r"(alo[mt][3])
                                 : "r"(aLoB + sw));
                }
                MMA_PASS(alo, bhi)
            }
#undef MMA_PASS
        }
    }

#pragma unroll
    for (int mt = 0; mt < 4; mt++) {
        int row = m0 + wm + mt * 16 + (lane >> 2);
#pragma unroll
        for (int nt = 0; nt < 4; nt++) {
            int col = n0 + wn + nt * 8 + (lane & 3) * 2;
            float2 v0 = make_float2(acc[mt][nt][0], acc[mt][nt][1]);
            float2 v1 = make_float2(acc[mt][nt][2], acc[mt][nt][3]);
            if (bias) {
                float b0 = bias[col], b1 = bias[col + 1];
                v0.x += b0; v0.y += b1; v1.x += b0; v1.y += b1;
            }
            *(float2*)&C[(size_t)row * ldc + col] = v0;
            *(float2*)&C[(size_t)(row + 8) * ldc + col] = v1;
        }
    }
}

// ---------------- fused conv + SiLU + softplus + SSM scan + gate + RMSnorm ------
__global__ void __launch_bounds__(512, 1) scan_kernel(
    const float* __restrict__ cwh, const float* __restrict__ cbh,
    const float* __restrict__ dtbh, const float* __restrict__ Alh,
    const float* __restrict__ Dh_, const float* __restrict__ nwh,
    const float* __restrict__ cwv, const float* __restrict__ cbv,
    const float* __restrict__ dtbv, const float* __restrict__ Alv,
    const float* __restrict__ Dv_, const float* __restrict__ nwv)
{
    const int tid  = threadIdx.x;
    const int head = tid >> 6;
    const int dir  = blockIdx.x >> 9;
    const int s    = blockIdx.x & 511;

    const float* Z       = dir ? g_Zv : g_Zh;
    const float* conv_w  = dir ? cwv : cwh;
    const float* conv_b  = dir ? cbv : cbh;
    const float* dt_bias = dir ? dtbv : dtbh;
    const float* A_log   = dir ? Alv : Alh;
    const float* Dvv     = dir ? Dv_ : Dh_;
    const float* norm_w  = dir ? nwv : nwh;
    const int ycol_off   = dir ? 0 : 512;

    int base, stride;
    if (dir) { int b = s >> 6, w = s & 63; base = b * 4096 + w; stride = 64; }
    else     { base = s * 64; stride = 1; }

    __shared__ __align__(16) float ring[8][CONV_CH];
    __shared__ __align__(16) float zbuf[4][512];
    __shared__ __align__(16) float dtbuf[4][8];
    __shared__ __align__(16) float Bsh[64];
    __shared__ __align__(16) float Csh[64];
    __shared__ float dt_s[8], dA_s[8], Aneg_s[8], dtb_s[8];
    __shared__ float red[16];

    for (int i = tid; i < 8 * CONV_CH; i += 512) (&ring[0][0])[i] = 0.f;
    if (tid < 8) { Aneg_s[tid] = -expf(A_log[tid]); dtb_s[tid] = dt_bias[tid]; }

    const float w0 = conv_w[tid * 4 + 0], w1 = conv_w[tid * 4 + 1];
    const float w2 = conv_w[tid * 4 + 2], w3 = conv_w[tid * 4 + 3];
    const float cb = conv_b[tid];
    float u0 = 0.f, u1 = 0.f, u2 = 0.f, u3 = 0.f, cb2 = 0.f;
    const int c2 = 512 + tid;
    if (tid < 128) {
        u0 = conv_w[c2 * 4 + 0]; u1 = conv_w[c2 * 4 + 1];
        u2 = conv_w[c2 * 4 + 2]; u3 = conv_w[c2 * 4 + 3];
        cb2 = conv_b[c2];
    }
    const float Dhv = Dvv[head];
    const float nw = norm_w[tid];

    ull h2[32];
#pragma unroll
    for (int n = 0; n < 32; n++) h2[n] = pack2(0.f, 0.f);

    const uint32_t ring_b = smem_u32(&ring[0][0]);
    const uint32_t zbuf_b = smem_u32(&zbuf[0][0]);
    const uint32_t dtb_b  = smem_u32(&dtbuf[0][0]);

    auto prefetch = [&](int tt) {
        if (tt < SEQ) {
            const float* row = Z + (size_t)(base + tt * stride) * NPAD1;
            if (tid < 160)       CP16(ring_b + (tt & 7) * (CONV_CH * 4) + tid * 16, row + 512 + tid * 4);
            else if (tid < 288)  CP16(zbuf_b + (tt & 3) * 2048 + (tid - 160) * 16, row + (tid - 160) * 4);
            else if (tid < 290)  CP16(dtb_b + (tt & 3) * 32 + (tid - 288) * 16, row + 1152 + (tid - 288) * 4);
        }
        CP_COMMIT();
    };

    __syncthreads();
    prefetch(0);
    prefetch(1);

    for (int t = 0; t < SEQ; t++) {
        if (t < SEQ - 1) CP_WAIT(1); else CP_WAIT(0);
        __syncthreads();
        prefetch(t + 2);

        const int slot = t & 7;
        if (tid < 8) {
            float draw = dtbuf[t & 3][tid] + dtb_s[tid];
            float dt = (draw > 20.f) ? draw : log1pf(expf(draw));
            dt_s[tid] = dt;
            dA_s[tid] = expf(dt * Aneg_s[tid]);
        }

        const int s0 = (t + 5) & 7, s1 = (t + 6) & 7, s2 = (t + 7) & 7, s3 = slot;
        float xv = cb;
        xv = fmaf(ring[s0][tid], w0, xv);
        xv = fmaf(ring[s1][tid], w1, xv);
        xv = fmaf(ring[s2][tid], w2, xv);
        xv = fmaf(ring[s3][tid], w3, xv);
        xv = xv / (1.f + expf(-xv));
        if (tid < 128) {
            float v = cb2;
            v = fmaf(ring[s0][c2], u0, v);
            v = fmaf(ring[s1][c2], u1, v);
            v = fmaf(ring[s2][c2], u2, v);
            v = fmaf(ring[s3][c2], u3, v);
            v = v / (1.f + expf(-v));
            if (tid < 64) Bsh[tid] = v; else Csh[tid - 64] = v;
        }
        __syncthreads();

        const float dA  = dA_s[head];
        const float dtx = dt_s[head] * xv;
        const ull dA2  = pack2(dA, dA);
        const ull dtx2 = pack2(dtx, dtx);
        ull y2 = pack2(0.f, 0.f);
        const ull* B2 = (const ull*)Bsh;
        const ull* C2 = (const ull*)Csh;
#pragma unroll
        for (int n = 0; n < 32; n++) {
            ull tb;
            MUL_X2(tb, dtx2, B2[n]);
            FMA_X2(h2[n], h2[n], dA2, tb);
            FMA_X2(y2, h2[n], C2[n], y2);
        }
        float ylo, yhi;
        asm("mov.b64 {%0, %1}, %2;" : "=f"(ylo), "=f"(yhi) : "l"(y2));
        float y = ylo + yhi;
        y = fmaf(xv, Dhv, y);

        const float z = zbuf[t & 3][tid];
        float g = y * (z / (1.f + expf(-z)));
        float ss = g * g;
#pragma unroll
        for (int o = 16; o; o >>= 1) ss += __shfl_xor_sync(0xffffffffu, ss, o);
        if ((tid & 31) == 0) red[tid >> 5] = ss;
        __syncthreads();
        float v = red[tid & 15];
#pragma unroll
        for (int o = 8; o; o >>= 1) v += __shfl_xor_sync(0xffffffffu, v, o);
        float s_inv = rsqrtf(v * (1.0f / 512.0f) + 1e-5f);

        float val = g * s_inv * nw;
        g_Y[(size_t)(base + t * stride) * KFIN + ycol_off + tid] = __float2half(val);
    }
}

// ---------------- fold fc_w into out_w -----------------------------------------
__global__ void __launch_bounds__(256) wcomb_kernel(
    const float* __restrict__ mh_out_w, const float* __restrict__ mv_out_w,
    const float* __restrict__ fc_w)
{
    const int d  = blockIdx.x;
    const int k0 = blockIdx.y * 64;
    const int nb = blockIdx.z * 32;
    const float* ow = d ? mh_out_w : mv_out_w;
    const int fo = d ? 512 : 0;
    __shared__ float ows[64][65];
    __shared__ float fs[32][65];
    const int kk = threadIdx.x & 63;
    const int ng = threadIdx.x >> 6;
    float acc[8];
#pragma unroll
    for (int i = 0; i < 8; i++) acc[i] = 0.f;

    for (int jo = 0; jo < 256; jo += 64) {
        for (int idx = threadIdx.x; idx < 64 * 64; idx += 256) {
            int j = idx >> 6, c = idx & 63;
            ows[j][c] = ow[(size_t)(jo + j) * 512 + k0 + c];
        }
        for (int idx = threadIdx.x; idx < 32 * 64; idx += 256) {
            int n = idx >> 6, jj = idx & 63;
            fs[n][jj] = fc_w[(size_t)(nb + n) * 1024 + fo + jo + jj] +
                        fc_w[(size_t)(nb + n) * 1024 + fo + 256 + jo + jj];
        }
        __syncthreads();
#pragma unroll 4
        for (int j = 0; j < 64; j++) {
            float o = ows[j][kk];
#pragma unroll
            for (int i = 0; i < 8; i++)
                acc[i] = fmaf(o, fs[ng * 8 + i][j], acc[i]);
        }
        __syncthreads();
    }
#pragma unroll
    for (int i = 0; i < 8; i++) {
        float val = acc[i];
        __half hh = __float2half(val);
        size_t idx = (size_t)(nb + ng * 8 + i) * KFIN + d * 512 + (k0 + kk);
        g_WcBhi[idx] = hh;
        g_WcBlo[idx] = __float2half(val - __half2float(hh));
    }
}

// ---------------- launch ----------------
extern "C" void kernel_launch(void* const* d_in, const int* in_sizes, int n_in,
                              void* d_out, int out_size)
{
    (void)in_sizes; (void)n_in; (void)out_size;
    const float* x          = (const float*)d_in[0];
    const float* mh_in_w    = (const float*)d_in[1];
    const float* mh_conv_w  = (const float*)d_in[2];
    const float* mh_conv_b  = (const float*)d_in[3];
    const float* mh_dt_bias = (const float*)d_in[4];
    const float* mh_A_log   = (const float*)d_in[5];
    const float* mh_D       = (const float*)d_in[6];
    const float* mh_norm_w  = (const float*)d_in[7];
    const float* mh_out_w   = (const float*)d_in[8];
    const float* mv_in_w    = (const float*)d_in[9];
    const float* mv_conv_w  = (const float*)d_in[10];
    const float* mv_conv_b  = (const float*)d_in[11];
    const float* mv_dt_bias = (const float*)d_in[12];
    const float* mv_A_log   = (const float*)d_in[13];
    const float* mv_D       = (const float*)d_in[14];
    const float* mv_norm_w  = (const float*)d_in[15];
    const float* mv_out_w   = (const float*)d_in[16];
    const float* fc_w       = (const float*)d_in[17];
    const float* fc_b       = (const float*)d_in[18];
    float* out = (float*)d_out;

    float *Zh, *Zv;
    __half *Xhi, *Xlo, *Whhi, *Whlo, *Wvhi, *Wvlo, *Y, *WcBhi, *WcBlo;
    cudaGetSymbolAddress((void**)&Zh,   g_Zh);
    cudaGetSymbolAddress((void**)&Zv,   g_Zv);
    cudaGetSymbolAddress((void**)&Xhi,  g_Xhi);
    cudaGetSymbolAddress((void**)&Xlo,  g_Xlo);
    cudaGetSymbolAddress((void**)&Whhi, g_Whhi);
    cudaGetSymbolAddress((void**)&Whlo, g_Whlo);
    cudaGetSymbolAddress((void**)&Wvhi, g_Wvhi);
    cudaGetSymbolAddress((void**)&Wvlo, g_Wvlo);
    cudaGetSymbolAddress((void**)&Y,    g_Y);
    cudaGetSymbolAddress((void**)&WcBhi, g_WcBhi);
    cudaGetSymbolAddress((void**)&WcBlo, g_WcBlo);

    cudaFuncSetAttribute(gemm_mma, cudaFuncAttributeMaxDynamicSharedMemorySize, GSMEM);

    cvt_x_kernel<<<NTOK * D_MODEL / 4 / 256, 256>>>(x);
    prep_w_kernel<<<dim3((NPAD1 * D_MODEL + 255) / 256, 2), 256>>>(mh_in_w, mv_in_w);
    wcomb_kernel<<<dim3(2, 8, 8), 256>>>(mh_out_w, mv_out_w, fc_w);

    // both in-proj GEMMs in one launch; dt tile (n0=1152) gets the 3rd pass
    gemm_mma<<<dim3(NTOK / BMg, NPAD1 / BNg, 2), 256, GSMEM>>>(
        Xhi, Xlo, Whhi, Whlo, Wvhi, Wvlo, Zh, Zv, D_MODEL, NPAD1, nullptr, 1152);

    // both scans in one launch
    scan_kernel<<<2 * NSEQ, 512>>>(
        mh_conv_w, mh_conv_b, mh_dt_bias, mh_A_log, mh_D, mh_norm_w,
        mv_conv_w, mv_conv_b, mv_dt_bias, mv_A_log, mv_D, mv_norm_w);

    // final fused output GEMM (2-term only; error lands directly on output)
    gemm_mma<<<dim3(NTOK / BMg, D_MODEL / BNg, 1), 256, GSMEM>>>(
        Y, Y, WcBhi, WcBlo, WcBhi, WcBlo, out, out, KFIN, D_MODEL, fc_b, -1);
}